// round 5
// baseline (speedup 1.0000x reference)
#include <cuda_runtime.h>

#define DV 160
#define HV 192
#define WV 160
#define VOL (DV * HV * WV)     // 4,915,200
#define W4  (WV / 4)           // 40
#define VOL4 (VOL / 4)         // 1,228,800
#define SLICE (HV * WV)

// Generic zero-padding trilinear for the 3-channel flow1 volume.
// Only reached for the handful of voxels near the origin (stage-1 coords are
// effectively un-normalized twice, so >99.99% of voxels are fully OOB).
__device__ __noinline__ void tri3_slow(const float* __restrict__ vol,
                                       float ix, float iy, float iz,
                                       float* __restrict__ o) {
    float x0f = floorf(ix), y0f = floorf(iy), z0f = floorf(iz);
    float tx = ix - x0f, ty = iy - y0f, tz = iz - z0f;
    int x0 = (int)x0f, y0 = (int)y0f, z0 = (int)z0f;
    float wx[2] = {1.f - tx, tx};
    float wy[2] = {1.f - ty, ty};
    float wz[2] = {1.f - tz, tz};
#pragma unroll
    for (int dz = 0; dz < 2; dz++) {
        int zc = z0 + dz;
        if (zc < 0 || zc >= DV) continue;
#pragma unroll
        for (int dy = 0; dy < 2; dy++) {
            int yc = y0 + dy;
            if (yc < 0 || yc >= HV) continue;
            int base = (zc * HV + yc) * WV;
            float wzy = wz[dz] * wy[dy];
#pragma unroll
            for (int dx = 0; dx < 2; dx++) {
                int xc = x0 + dx;
                if (xc < 0 || xc >= WV) continue;
                float wgt = wzy * wx[dx];
                int off = base + xc;
                o[0] = fmaf(__ldg(vol + off),           wgt, o[0]);
                o[1] = fmaf(__ldg(vol + VOL + off),     wgt, o[1]);
                o[2] = fmaf(__ldg(vol + 2 * VOL + off), wgt, o[2]);
            }
        }
    }
}

// Slow path for src sampling (border / partially-OOB voxels only).
__device__ __noinline__ float tri1_slow(const float* __restrict__ vol,
                                        float ix, float iy, float iz,
                                        int x0, int y0, int z0,
                                        float tx, float ty, float tz) {
    float wx[2] = {1.f - tx, tx};
    float wy[2] = {1.f - ty, ty};
    float wz[2] = {1.f - tz, tz};
    float acc = 0.f;
#pragma unroll
    for (int dz = 0; dz < 2; dz++) {
        int zc = z0 + dz;
        if (zc < 0 || zc >= DV) continue;
#pragma unroll
        for (int dy = 0; dy < 2; dy++) {
            int yc = y0 + dy;
            if (yc < 0 || yc >= HV) continue;
            int base = (zc * HV + yc) * WV;
            float wzy = wz[dz] * wy[dy];
#pragma unroll
            for (int dx = 0; dx < 2; dx++) {
                int xc = x0 + dx;
                if (xc < 0 || xc >= WV) continue;
                acc = fmaf(__ldg(vol + base + xc), wzy * wx[dx], acc);
            }
        }
    }
    return acc;
}

__device__ __forceinline__ float tri1(const float* __restrict__ v,
                                      float ix, float iy, float iz) {
    float x0f = floorf(ix), y0f = floorf(iy), z0f = floorf(iz);
    float tx = ix - x0f, ty = iy - y0f, tz = iz - z0f;
    int x0 = (int)x0f, y0 = (int)y0f, z0 = (int)z0f;
    if (x0 >= 0 && x0 < WV - 1 &&
        y0 >= 0 && y0 < HV - 1 &&
        z0 >= 0 && z0 < DV - 1) {
        // Fully interior: 8 unconditional gathers, lerp tree (7 lerps).
        const float* p0 = v + (z0 * HV + y0) * WV + x0;
        const float* p1 = p0 + SLICE;
        float v000 = __ldg(p0),      v001 = __ldg(p0 + 1);
        float v010 = __ldg(p0 + WV), v011 = __ldg(p0 + WV + 1);
        float v100 = __ldg(p1),      v101 = __ldg(p1 + 1);
        float v110 = __ldg(p1 + WV), v111 = __ldg(p1 + WV + 1);
        float c00 = fmaf(v001 - v000, tx, v000);
        float c01 = fmaf(v011 - v010, tx, v010);
        float c10 = fmaf(v101 - v100, tx, v100);
        float c11 = fmaf(v111 - v110, tx, v110);
        float c0  = fmaf(c01 - c00, ty, c00);
        float c1  = fmaf(c11 - c10, ty, c10);
        return fmaf(c1 - c0, tz, c0);
    }
    // Fully OOB -> 0 (zeros padding)
    if (x0 <= -2 || x0 >= WV || y0 <= -2 || y0 >= HV || z0 <= -2 || z0 >= DV)
        return 0.f;
    return tri1_slow(v, ix, iy, iz, x0, y0, z0, tx, ty, tz);
}

__global__ void __launch_bounds__(256)
spatial_transformer_fused4(const float* __restrict__ src,
                           const float* __restrict__ flow1,
                           const float* __restrict__ flow2,
                           const float* __restrict__ rf_ptr,
                           float* __restrict__ out) {
    int tid = blockIdx.x * blockDim.x + threadIdx.x;
    if (tid >= VOL4) return;

    // Each thread handles 4 consecutive-x voxels.
    int w4 = tid % W4;
    int t  = tid / W4;
    int h  = t % HV;
    int d  = t / HV;
    int idx = tid * 4;                // linear voxel index of lane 0
    float wf0 = (float)(w4 * 4);
    float hf  = (float)h;
    float df  = (float)d;

    float rf = __ldg(rf_ptr);

    const float4 fz = __ldg((const float4*)(flow2) + tid);            // ch0 -> D
    const float4 fy = __ldg((const float4*)(flow2 + VOL) + tid);      // ch1 -> H
    const float4 fx = __ldg((const float4*)(flow2 + 2 * VOL) + tid);  // ch2 -> W

    float f2z[4] = {fz.x, fz.y, fz.z, fz.w};
    float f2y[4] = {fy.x, fy.y, fy.z, fy.w};
    float f2x[4] = {fx.x, fx.y, fx.z, fx.w};

    float of0[4], of1[4], of2[4], img[4];

    // Stage-2 coordinate constants: ix2 = nl * S/(S-1) - 0.5
    const float CD = (float)DV / (float)(DV - 1);
    const float CH = (float)HV / (float)(HV - 1);
    const float CW = (float)WV / (float)(WV - 1);

#pragma unroll
    for (int j = 0; j < 4; j++) {
        // ---- Stage 1: flow1 warped by grid+flow2*rf (treated as normalized
        // coords -> almost always fully OOB -> zero).
        float gz = df        + f2z[j] * rf;
        float gy = hf        + f2y[j] * rf;
        float gx = wf0 + (float)j + f2x[j] * rf;
        float iz1 = fmaf(gz, 80.f, 79.5f);   // ((gz+1)*160-1)/2
        float iy1 = fmaf(gy, 96.f, 95.5f);   // ((gy+1)*192-1)/2
        float ix1 = fmaf(gx, 80.f, 79.5f);

        float fw[3] = {0.f, 0.f, 0.f};
        if (ix1 >= -1.f && ix1 < (float)WV &&
            iy1 >= -1.f && iy1 < (float)HV &&
            iz1 >= -1.f && iz1 < (float)DV) {
            tri3_slow(flow1, ix1, iy1, iz1, fw);
        }
        of0[j] = fw[0] + f2z[j];
        of1[j] = fw[1] + f2y[j];
        of2[j] = fw[2] + f2x[j];

        // ---- Stage 2: resample src at grid + out_flow*rf (renormalized).
        float nl0 = df        + of0[j] * rf;
        float nl1 = hf        + of1[j] * rf;
        float nl2 = wf0 + (float)j + of2[j] * rf;
        float iz2 = fmaf(nl0, CD, -0.5f);
        float iy2 = fmaf(nl1, CH, -0.5f);
        float ix2 = fmaf(nl2, CW, -0.5f);

        img[j] = tri1(src, ix2, iy2, iz2);
    }

    // ---- Vectorized stores: deform_2_img [V], out_flow [3V].
    ((float4*)(out))[tid]                 = make_float4(img[0], img[1], img[2], img[3]);
    ((float4*)(out + VOL))[tid]           = make_float4(of0[0], of0[1], of0[2], of0[3]);
    ((float4*)(out + 2 * VOL))[tid]       = make_float4(of1[0], of1[1], of1[2], of1[3]);
    ((float4*)(out + 3 * VOL))[tid]       = make_float4(of2[0], of2[1], of2[2], of2[3]);
}

extern "C" void kernel_launch(void* const* d_in, const int* in_sizes, int n_in,
                              void* d_out, int out_size) {
    const float* src   = (const float*)d_in[0];
    const float* flow1 = (const float*)d_in[1];
    const float* flow2 = (const float*)d_in[2];
    // d_in[3] = meshgrid (recomputed in-kernel)
    const float* rf    = (const float*)d_in[4];
    float* out = (float*)d_out;

    int threads = 256;
    int blocks = (VOL4 + threads - 1) / threads;   // 4800
    spatial_transformer_fused4<<<blocks, threads>>>(src, flow1, flow2, rf, out);
}

// round 6
// speedup vs baseline: 1.0296x; 1.0296x over previous
#include <cuda_runtime.h>

#define DV 160
#define HV 192
#define WV 160
#define VOL (DV * HV * WV)     // 4,915,200
#define W4  (WV / 4)           // 40
#define VOL4 (VOL / 4)         // 1,228,800
#define SLICE (HV * WV)

// Generic zero-padding trilinear for the 3-channel flow1 volume (rare path:
// stage-1 coords are effectively un-normalized twice -> >99.99% fully OOB).
__device__ __noinline__ void tri3_slow(const float* __restrict__ vol,
                                       float ix, float iy, float iz,
                                       float* __restrict__ o) {
    float x0f = floorf(ix), y0f = floorf(iy), z0f = floorf(iz);
    float tx = ix - x0f, ty = iy - y0f, tz = iz - z0f;
    int x0 = (int)x0f, y0 = (int)y0f, z0 = (int)z0f;
    float wx[2] = {1.f - tx, tx};
    float wy[2] = {1.f - ty, ty};
    float wz[2] = {1.f - tz, tz};
#pragma unroll
    for (int dz = 0; dz < 2; dz++) {
        int zc = z0 + dz;
        if (zc < 0 || zc >= DV) continue;
#pragma unroll
        for (int dy = 0; dy < 2; dy++) {
            int yc = y0 + dy;
            if (yc < 0 || yc >= HV) continue;
            int base = (zc * HV + yc) * WV;
            float wzy = wz[dz] * wy[dy];
#pragma unroll
            for (int dx = 0; dx < 2; dx++) {
                int xc = x0 + dx;
                if (xc < 0 || xc >= WV) continue;
                float wgt = wzy * wx[dx];
                int off = base + xc;
                o[0] = fmaf(__ldg(vol + off),           wgt, o[0]);
                o[1] = fmaf(__ldg(vol + VOL + off),     wgt, o[1]);
                o[2] = fmaf(__ldg(vol + 2 * VOL + off), wgt, o[2]);
            }
        }
    }
}

// Slow path for src sampling (border / partially-OOB voxels only).
__device__ __noinline__ float tri1_slow(const float* __restrict__ vol,
                                        int x0, int y0, int z0,
                                        float tx, float ty, float tz) {
    float wx[2] = {1.f - tx, tx};
    float wy[2] = {1.f - ty, ty};
    float wz[2] = {1.f - tz, tz};
    float acc = 0.f;
#pragma unroll
    for (int dz = 0; dz < 2; dz++) {
        int zc = z0 + dz;
        if (zc < 0 || zc >= DV) continue;
#pragma unroll
        for (int dy = 0; dy < 2; dy++) {
            int yc = y0 + dy;
            if (yc < 0 || yc >= HV) continue;
            int base = (zc * HV + yc) * WV;
            float wzy = wz[dz] * wy[dy];
#pragma unroll
            for (int dx = 0; dx < 2; dx++) {
                int xc = x0 + dx;
                if (xc < 0 || xc >= WV) continue;
                acc = fmaf(__ldg(vol + base + xc), wzy * wx[dx], acc);
            }
        }
    }
    return acc;
}

// Interior fast path: per (z,y)-row, ONE 16B-aligned float4 load covers both
// x-corners for k = x0&3 in {0,1,2}; k==3 needs one predicated scalar fix-up.
// Halves gather L1 wavefronts vs 8 scalar loads (lines charged once, not twice).
__device__ __forceinline__ float tri1(const float* __restrict__ v,
                                      float ix, float iy, float iz) {
    float x0f = floorf(ix), y0f = floorf(iy), z0f = floorf(iz);
    float tx = ix - x0f, ty = iy - y0f, tz = iz - z0f;
    int x0 = (int)x0f, y0 = (int)y0f, z0 = (int)z0f;
    if (x0 >= 0 && x0 < WV - 1 &&
        y0 >= 0 && y0 < HV - 1 &&
        z0 >= 0 && z0 < DV - 1) {
        int xb = x0 & ~3;          // 16B-aligned, xb <= 156 -> xb+3 <= 159 in-bounds
        int k  = x0 & 3;
        const float* r00 = v + (z0 * HV + y0) * WV + xb;
        const float* r01 = r00 + WV;
        const float* r10 = r00 + SLICE;
        const float* r11 = r10 + WV;
        float4 f00 = __ldg((const float4*)r00);
        float4 f01 = __ldg((const float4*)r01);
        float4 f10 = __ldg((const float4*)r10);
        float4 f11 = __ldg((const float4*)r11);

        // Fix-up for k==3: x0+1 = xb+4 (in-bounds since x0 <= 158).
        float e00 = 0.f, e01 = 0.f, e10 = 0.f, e11 = 0.f;
        int koff = x0 + 1 - xb;    // dummy use to keep indexing explicit
        (void)koff;
        if (k == 3) {
            const float* q = v + (z0 * HV + y0) * WV + x0 + 1;
            e00 = __ldg(q);
            e01 = __ldg(q + WV);
            e10 = __ldg(q + SLICE);
            e11 = __ldg(q + SLICE + WV);
        }

        bool k0 = (k == 0), k1 = (k == 1), k2 = (k == 2);
        float a00 = k0 ? f00.x : k1 ? f00.y : k2 ? f00.z : f00.w;
        float b00 = k0 ? f00.y : k1 ? f00.z : k2 ? f00.w : e00;
        float a01 = k0 ? f01.x : k1 ? f01.y : k2 ? f01.z : f01.w;
        float b01 = k0 ? f01.y : k1 ? f01.z : k2 ? f01.w : e01;
        float a10 = k0 ? f10.x : k1 ? f10.y : k2 ? f10.z : f10.w;
        float b10 = k0 ? f10.y : k1 ? f10.z : k2 ? f10.w : e10;
        float a11 = k0 ? f11.x : k1 ? f11.y : k2 ? f11.z : f11.w;
        float b11 = k0 ? f11.y : k1 ? f11.z : k2 ? f11.w : e11;

        float c00 = fmaf(b00 - a00, tx, a00);
        float c01 = fmaf(b01 - a01, tx, a01);
        float c10 = fmaf(b10 - a10, tx, a10);
        float c11 = fmaf(b11 - a11, tx, a11);
        float c0  = fmaf(c01 - c00, ty, c00);
        float c1  = fmaf(c11 - c10, ty, c10);
        return fmaf(c1 - c0, tz, c0);
    }
    // Fully OOB -> 0 (zeros padding)
    if (x0 <= -2 || x0 >= WV || y0 <= -2 || y0 >= HV || z0 <= -2 || z0 >= DV)
        return 0.f;
    return tri1_slow(v, x0, y0, z0, tx, ty, tz);
}

__global__ void __launch_bounds__(256)
spatial_transformer_fused4(const float* __restrict__ src,
                           const float* __restrict__ flow1,
                           const float* __restrict__ flow2,
                           const float* __restrict__ rf_ptr,
                           float* __restrict__ out) {
    int tid = blockIdx.x * blockDim.x + threadIdx.x;
    if (tid >= VOL4) return;

    // Each thread handles 4 consecutive-x voxels.
    int w4 = tid % W4;
    int t  = tid / W4;
    int h  = t % HV;
    int d  = t / HV;
    float wf0 = (float)(w4 * 4);
    float hf  = (float)h;
    float df  = (float)d;

    float rf = __ldg(rf_ptr);

    const float4 fz = __ldg((const float4*)(flow2) + tid);            // ch0 -> D
    const float4 fy = __ldg((const float4*)(flow2 + VOL) + tid);      // ch1 -> H
    const float4 fx = __ldg((const float4*)(flow2 + 2 * VOL) + tid);  // ch2 -> W

    float f2z[4] = {fz.x, fz.y, fz.z, fz.w};
    float f2y[4] = {fy.x, fy.y, fy.z, fy.w};
    float f2x[4] = {fx.x, fx.y, fx.z, fx.w};

    float of0[4], of1[4], of2[4], img[4];

    // Stage-2 coordinate constants: ix2 = nl * S/(S-1) - 0.5
    const float CD = (float)DV / (float)(DV - 1);
    const float CH = (float)HV / (float)(HV - 1);
    const float CW = (float)WV / (float)(WV - 1);

#pragma unroll
    for (int j = 0; j < 4; j++) {
        // ---- Stage 1: flow1 warped by grid+flow2*rf (treated as normalized
        // coords -> almost always fully OOB -> zero).
        float gz = df             + f2z[j] * rf;
        float gy = hf             + f2y[j] * rf;
        float gx = wf0 + (float)j + f2x[j] * rf;
        float iz1 = fmaf(gz, 80.f, 79.5f);   // ((gz+1)*160-1)/2
        float iy1 = fmaf(gy, 96.f, 95.5f);   // ((gy+1)*192-1)/2
        float ix1 = fmaf(gx, 80.f, 79.5f);

        float fw[3] = {0.f, 0.f, 0.f};
        if (ix1 >= -1.f && ix1 < (float)WV &&
            iy1 >= -1.f && iy1 < (float)HV &&
            iz1 >= -1.f && iz1 < (float)DV) {
            tri3_slow(flow1, ix1, iy1, iz1, fw);
        }
        of0[j] = fw[0] + f2z[j];
        of1[j] = fw[1] + f2y[j];
        of2[j] = fw[2] + f2x[j];

        // ---- Stage 2: resample src at grid + out_flow*rf (renormalized).
        float nl0 = df             + of0[j] * rf;
        float nl1 = hf             + of1[j] * rf;
        float nl2 = wf0 + (float)j + of2[j] * rf;
        float iz2 = fmaf(nl0, CD, -0.5f);
        float iy2 = fmaf(nl1, CH, -0.5f);
        float ix2 = fmaf(nl2, CW, -0.5f);

        img[j] = tri1(src, ix2, iy2, iz2);
    }

    // ---- Vectorized stores: deform_2_img [V], out_flow [3V].
    ((float4*)(out))[tid]           = make_float4(img[0], img[1], img[2], img[3]);
    ((float4*)(out + VOL))[tid]     = make_float4(of0[0], of0[1], of0[2], of0[3]);
    ((float4*)(out + 2 * VOL))[tid] = make_float4(of1[0], of1[1], of1[2], of1[3]);
    ((float4*)(out + 3 * VOL))[tid] = make_float4(of2[0], of2[1], of2[2], of2[3]);
}

extern "C" void kernel_launch(void* const* d_in, const int* in_sizes, int n_in,
                              void* d_out, int out_size) {
    const float* src   = (const float*)d_in[0];
    const float* flow1 = (const float*)d_in[1];
    const float* flow2 = (const float*)d_in[2];
    // d_in[3] = meshgrid (recomputed in-kernel)
    const float* rf    = (const float*)d_in[4];
    float* out = (float*)d_out;

    int threads = 256;
    int blocks = (VOL4 + threads - 1) / threads;   // 4800
    spatial_transformer_fused4<<<blocks, threads>>>(src, flow1, flow2, rf, out);
}